// round 17
// baseline (speedup 1.0000x reference)
#include <cuda_runtime.h>
#include <cstdint>

typedef unsigned int u32;

// ---------------------------------------------------------------------------
// XNOR-net CNN forward, GB300. Binary convs exact via bitpack + popcount.
// 128-thread CTAs, weights in smem, static unrolled pixel loops, pixel-split
// grids for occupancy. Intermediates are 1-bit tensors in __device__ globals.
// ---------------------------------------------------------------------------

// Bit tensors: layout [b][y][x][cw], bit j of word cw = channel cw*32+j
__device__ __align__(16) unsigned g_bits1[128 * 32 * 32 * 4];
__device__ __align__(16) unsigned g_bits2[128 * 16 * 16 * 4];
__device__ __align__(16) unsigned g_bits3[128 * 16 * 16 * 8];
__device__ __align__(16) unsigned g_bits4[128 * 8 * 8 * 8];
__device__ __align__(16) unsigned g_bits5[128 * 8 * 8 * 16];
__device__ float g_h6[128 * 4 * 4 * 512];

// Packed weights: uint4 index [(t*G + g)*COUT + co] holds cin-words g*4..g*4+3
__device__ __align__(16) unsigned g_pw2[9 * 4 * 128];
__device__ __align__(16) unsigned g_pw3[9 * 4 * 256];
__device__ __align__(16) unsigned g_pw4[9 * 8 * 256];
__device__ __align__(16) unsigned g_pw5[9 * 8 * 512];
__device__ __align__(16) unsigned g_pw6[9 * 16 * 512];

// ---------------------------------------------------------------------------
// Weight bit-packing, all 5 layers in one launch.
// ---------------------------------------------------------------------------
__device__ __forceinline__ void pack_one(const float* __restrict__ w, unsigned* out,
                                         int Cin, int Cout, int rel)
{
    int co = rel % Cout;
    int q = rel / Cout;
    int cwn = Cin >> 5;
    int cw = q % cwn;
    int t = q / cwn;
    unsigned word = 0;
#pragma unroll 8
    for (int j = 0; j < 32; j++) {
        float v = w[(t * Cin + cw * 32 + j) * Cout + co];
        word |= (v > 0.f ? 1u : 0u) << j;
    }
    int G = cwn >> 2;
    int g = cw >> 2, k = cw & 3;
    out[((t * G + g) * Cout + co) * 4 + k] = word;
}

__global__ void __launch_bounds__(256) pack_all_kernel(
    const float* __restrict__ w2, const float* __restrict__ w3,
    const float* __restrict__ w4, const float* __restrict__ w5,
    const float* __restrict__ w6)
{
    int idx = blockIdx.x * 256 + threadIdx.x;
    if (idx < 4608)        pack_one(w2, g_pw2, 128, 128, idx);
    else if (idx < 13824)  pack_one(w3, g_pw3, 128, 256, idx - 4608);
    else if (idx < 32256)  pack_one(w4, g_pw4, 256, 256, idx - 13824);
    else if (idx < 69120)  pack_one(w5, g_pw5, 256, 512, idx - 32256);
    else if (idx < 142848) pack_one(w6, g_pw6, 512, 512, idx - 69120);
}

// ---------------------------------------------------------------------------
// conv1: fp32 3x3 conv 3->128 SAME, +b1, relu, BN, sign -> bitpack
// ---------------------------------------------------------------------------
__global__ void __launch_bounds__(128) conv1_kernel(
    const float* __restrict__ x, const float* __restrict__ w1,
    const float* __restrict__ b1, const float* __restrict__ s1,
    const float* __restrict__ bi1)
{
    __shared__ __align__(16) float sw[27 * 128];
    __shared__ float sb[128], ss[128], sbi[128];
    int tid = threadIdx.x;
    for (int i = tid; i < 27 * 128; i += 128) sw[i] = w1[i];
    sb[tid] = b1[tid]; ss[tid] = s1[tid]; sbi[tid] = bi1[tid];
    __syncthreads();

    int pid = blockIdx.x * 128 + tid;
    int b = pid >> 10, y = (pid >> 5) & 31, xx = pid & 31;

    float in[27];
#pragma unroll
    for (int dy = 0; dy < 3; dy++)
#pragma unroll
        for (int dx = 0; dx < 3; dx++) {
            int iy = y + dy - 1, ix = xx + dx - 1;
            bool v = (iy >= 0 && iy < 32 && ix >= 0 && ix < 32);
            const float* p = x + ((b * 32 + iy) * 32 + ix) * 3;
#pragma unroll
            for (int c = 0; c < 3; c++)
                in[(dy * 3 + dx) * 3 + c] = v ? p[c] : 0.f;
        }

#pragma unroll
    for (int chunk = 0; chunk < 4; chunk++) {
        unsigned word = 0;
#pragma unroll
        for (int jj = 0; jj < 8; jj++) {
            int co4 = chunk * 32 + jj * 4;
            float4 acc = make_float4(0.f, 0.f, 0.f, 0.f);
#pragma unroll
            for (int k = 0; k < 27; k++) {
                float4 wv = *reinterpret_cast<const float4*>(&sw[k * 128 + co4]);
                float iv = in[k];
                acc.x = fmaf(iv, wv.x, acc.x);
                acc.y = fmaf(iv, wv.y, acc.y);
                acc.z = fmaf(iv, wv.z, acc.z);
                acc.w = fmaf(iv, wv.w, acc.w);
            }
            float av[4] = {acc.x, acc.y, acc.z, acc.w};
#pragma unroll
            for (int e = 0; e < 4; e++) {
                int co = co4 + e;
                float v = fmaxf(av[e] + sb[co], 0.f);
                bool bit = fmaf(v, ss[co], sbi[co]) > 0.f;
                word |= (bit ? 1u : 0u) << (jj * 4 + e);
            }
        }
        g_bits1[pid * 4 + chunk] = word;
    }
}

// ---------------------------------------------------------------------------
// Common helpers
// ---------------------------------------------------------------------------
__device__ __forceinline__ int border_corr(int y, int x, int H, int W, const int S[9])
{
    int c = 0;
    if (y == 0)      c += S[0] + S[1] + S[2];
    if (y == H - 1)  c += S[6] + S[7] + S[8];
    if (x == 0) {
        c += S[0] + S[3] + S[6];
        if (y == 0)     c -= S[0];
        if (y == H - 1) c -= S[6];
    }
    if (x == W - 1) {
        c += S[2] + S[5] + S[8];
        if (y == 0)     c -= S[2];
        if (y == H - 1) c -= S[8];
    }
    return c;
}

__device__ __forceinline__ int popc4x(uint4 a, uint4 w)
{
    return __popc(a.x ^ w.x) + __popc(a.y ^ w.y) + __popc(a.z ^ w.z) + __popc(a.w ^ w.w);
}

// ---------------------------------------------------------------------------
// Binary conv. 128 threads (4 warps), warp = 32 couts (lane = co).
// Weights in smem; act in smem (broadcast reads); row-streamed windows.
// grid = (COUT/32, 128 imgs, PS row-slices). Static unrolled pixel loops.
// POOL path: quad (2x2 conv outputs -> max). Non-pool: horizontal pixel pair.
// ---------------------------------------------------------------------------
template <int W, int CW, int COUT, bool POOL, int LAYER, int PS>
__global__ void __launch_bounds__(128, 8) bconv3_kernel(
    const float* __restrict__ bn_s, const float* __restrict__ bn_b)
{
    constexpr int CIN = CW * 32;
    constexpr int G = CW / 4;
    constexpr int COW = COUT / 32;
    constexpr int HP = (W + 2) * (W + 2);
    constexpr int OH = POOL ? W / 2 : W;
    constexpr int OW = POOL ? W / 2 : W;
    constexpr bool FINAL = (LAYER == 6);
    // per-slice work items (quads or pairs), per-warp iterations
    constexpr int ROWS = OH / PS;                       // output rows per slice
    constexpr int NITEM = POOL ? ROWS * OW : ROWS * (W / 2);
    constexpr int NITER = NITEM / 4;
    static_assert(NITEM % 4 == 0, "items divisible by warps");

    const unsigned* in_bits;
    const unsigned* wp;
    unsigned* outb = nullptr;
    if constexpr (LAYER == 2)      { in_bits = g_bits1; wp = g_pw2; outb = g_bits2; }
    else if constexpr (LAYER == 3) { in_bits = g_bits2; wp = g_pw3; outb = g_bits3; }
    else if constexpr (LAYER == 4) { in_bits = g_bits3; wp = g_pw4; outb = g_bits4; }
    else if constexpr (LAYER == 5) { in_bits = g_bits4; wp = g_pw5; outb = g_bits5; }
    else                           { in_bits = g_bits5; wp = g_pw6; }

    __shared__ __align__(16) unsigned act[HP * CW];
    __shared__ __align__(16) uint4 wsm[9 * G * 32];

    const int tid = threadIdx.x, lane = tid & 31, warp = tid >> 5;
    const int cog = blockIdx.x, b = blockIdx.y, zs = blockIdx.z;
    const int co = cog * 32 + lane;

    // ---- weights -> smem ----
    const uint4* pw4 = reinterpret_cast<const uint4*>(wp);
    for (int i = tid; i < 9 * G * 32; i += 128) {
        int l = i & 31, q = i >> 5;
        wsm[i] = pw4[q * COUT + cog * 32 + l];
    }
    // ---- act -> smem (zero halo) ----
    for (int i = tid; i < HP * CW; i += 128)
        act[i] = 0;
    __syncthreads();
    {
        const uint4* src = reinterpret_cast<const uint4*>(in_bits) + (size_t)b * W * W * G;
        uint4* A4 = reinterpret_cast<uint4*>(act);
        for (int i = tid; i < W * W * G; i += 128) {
            int g = i % G, q = i / G;
            int xx = q % W, yy = q / W;
            A4[((yy + 1) * (W + 2) + (xx + 1)) * G + g] = src[i];
        }
    }
    __syncthreads();

    // ---- per-tap weight sign sums ----
    int S[9];
#pragma unroll
    for (int t = 0; t < 9; t++) {
        int p = 0;
#pragma unroll
        for (int g = 0; g < G; g++) {
            uint4 w = wsm[(t * G + g) * 32 + lane];
            p += __popc(w.x) + __popc(w.y) + __popc(w.z) + __popc(w.w);
        }
        S[t] = CIN - 2 * p;
    }
    const float scale = bn_s[co], bias = bn_b[co];

    const uint4* A = reinterpret_cast<const uint4*>(act);

    if constexpr (POOL) {
#pragma unroll 2
        for (int it = 0; it < NITER; it++) {
            const int i = warp + it * 4;
            const int oy = zs * ROWS + i / OW, ox = i % OW;
            const int iy = 2 * oy, ix = 2 * ox;
            int p00 = 0, p01 = 0, p10 = 0, p11 = 0;
#pragma unroll
            for (int g = 0; g < G; g++) {
                const uint4* P = A + (iy * (W + 2) + ix) * G + g;
#pragma unroll
                for (int r = 0; r < 4; r++) {
                    uint4 a0 = P[(r * (W + 2) + 0) * G];
                    uint4 a1 = P[(r * (W + 2) + 1) * G];
                    uint4 a2 = P[(r * (W + 2) + 2) * G];
                    uint4 a3 = P[(r * (W + 2) + 3) * G];
                    if (r < 3) {
                        uint4 w0 = wsm[((r * 3 + 0) * G + g) * 32 + lane];
                        uint4 w1 = wsm[((r * 3 + 1) * G + g) * 32 + lane];
                        uint4 w2 = wsm[((r * 3 + 2) * G + g) * 32 + lane];
                        p00 += popc4x(a0, w0) + popc4x(a1, w1) + popc4x(a2, w2);
                        p01 += popc4x(a1, w0) + popc4x(a2, w1) + popc4x(a3, w2);
                    }
                    if (r > 0) {
                        uint4 w0 = wsm[(((r - 1) * 3 + 0) * G + g) * 32 + lane];
                        uint4 w1 = wsm[(((r - 1) * 3 + 1) * G + g) * 32 + lane];
                        uint4 w2 = wsm[(((r - 1) * 3 + 2) * G + g) * 32 + lane];
                        p10 += popc4x(a0, w0) + popc4x(a1, w1) + popc4x(a2, w2);
                        p11 += popc4x(a1, w0) + popc4x(a2, w1) + popc4x(a3, w2);
                    }
                }
            }
            int s0 = 9 * CIN - 2 * p00 - border_corr(iy,     ix,     W, W, S);
            int s1 = 9 * CIN - 2 * p01 - border_corr(iy,     ix + 1, W, W, S);
            int s2 = 9 * CIN - 2 * p10 - border_corr(iy + 1, ix,     W, W, S);
            int s3 = 9 * CIN - 2 * p11 - border_corr(iy + 1, ix + 1, W, W, S);
            int m = max(0, max(max(s0, s1), max(s2, s3)));
            if constexpr (FINAL) {
                g_h6[((b * OH + oy) * OW + ox) * COUT + co] = fmaf((float)m, scale, bias);
            } else {
                bool bit = fmaf((float)m, scale, bias) > 0.f;
                unsigned wd = __ballot_sync(0xffffffffu, bit);
                if (lane == 0) outb[((b * OH + oy) * OW + ox) * COW + cog] = wd;
            }
        }
    } else {
        // horizontal pixel pairs, row-streamed 3x4 window, weights shared
#pragma unroll 2
        for (int it = 0; it < NITER; it++) {
            const int i = warp + it * 4;
            const int oy = zs * ROWS + i / (W / 2), ox = 2 * (i % (W / 2));
            int acc0 = 0, acc1 = 0;
#pragma unroll
            for (int g = 0; g < G; g++) {
                const uint4* P = A + (oy * (W + 2) + ox) * G + g;
#pragma unroll
                for (int r = 0; r < 3; r++) {
                    uint4 a0 = P[(r * (W + 2) + 0) * G];
                    uint4 a1 = P[(r * (W + 2) + 1) * G];
                    uint4 a2 = P[(r * (W + 2) + 2) * G];
                    uint4 a3 = P[(r * (W + 2) + 3) * G];
                    uint4 w0 = wsm[((r * 3 + 0) * G + g) * 32 + lane];
                    uint4 w1 = wsm[((r * 3 + 1) * G + g) * 32 + lane];
                    uint4 w2 = wsm[((r * 3 + 2) * G + g) * 32 + lane];
                    acc0 += popc4x(a0, w0) + popc4x(a1, w1) + popc4x(a2, w2);
                    acc1 += popc4x(a1, w0) + popc4x(a2, w1) + popc4x(a3, w2);
                }
            }
            int s0 = 9 * CIN - 2 * acc0 - border_corr(oy, ox,     W, W, S);
            int s1 = 9 * CIN - 2 * acc1 - border_corr(oy, ox + 1, W, W, S);
            bool bit0 = fmaf((float)max(s0, 0), scale, bias) > 0.f;
            bool bit1 = fmaf((float)max(s1, 0), scale, bias) > 0.f;
            unsigned w0 = __ballot_sync(0xffffffffu, bit0);
            unsigned w1 = __ballot_sync(0xffffffffu, bit1);
            if (lane == 0) {
                outb[((b * W + oy) * W + ox) * COW + cog] = w0;
                outb[((b * W + oy) * W + ox + 1) * COW + cog] = w1;
            }
        }
    }
}

// ---------------------------------------------------------------------------
// Dense (512->10 on last axis) + bias + softmax
// ---------------------------------------------------------------------------
__global__ void __launch_bounds__(128) dense_softmax_kernel(
    const float* __restrict__ dw, const float* __restrict__ db, float* __restrict__ out)
{
    __shared__ float sdw[512 * 10];
    __shared__ float sdb[10];
    int tid = threadIdx.x;
    for (int i = tid; i < 5120; i += 128) sdw[i] = dw[i];
    if (tid < 10) sdb[tid] = db[tid];
    __syncthreads();

    int r = blockIdx.x * 128 + tid;
    float acc[10];
#pragma unroll
    for (int d = 0; d < 10; d++) acc[d] = sdb[d];
    const float* h = g_h6 + (size_t)r * 512;
    for (int c = 0; c < 512; c++) {
        float hv = h[c];
#pragma unroll
        for (int d = 0; d < 10; d++) acc[d] = fmaf(hv, sdw[c * 10 + d], acc[d]);
    }
    float m = acc[0];
#pragma unroll
    for (int d = 1; d < 10; d++) m = fmaxf(m, acc[d]);
    float e[10], s = 0.f;
#pragma unroll
    for (int d = 0; d < 10; d++) { e[d] = expf(acc[d] - m); s += e[d]; }
    float inv = 1.f / s;
#pragma unroll
    for (int d = 0; d < 10; d++) out[r * 10 + d] = e[d] * inv;
}

// ---------------------------------------------------------------------------
// Launch
// ---------------------------------------------------------------------------
extern "C" void kernel_launch(void* const* d_in, const int* in_sizes, int n_in,
                              void* d_out, int out_size)
{
    const float *x = nullptr, *w1 = nullptr, *b1 = nullptr;
    const float *w2 = nullptr, *w3 = nullptr, *w4 = nullptr, *w5 = nullptr, *w6 = nullptr;
    const float *dw = nullptr, *db = nullptr;
    const float* bns[12] = {nullptr};
    int bn_idx = 0;

    for (int i = 0; i < n_in; i++) {
        const float* p = (const float*)d_in[i];
        int s = in_sizes[i];
        if (i == 0)              x = p;
        else if (s == 3456)      w1 = p;
        else if (i == 2)         b1 = p;
        else if (s == 147456)    w2 = p;
        else if (s == 294912)    w3 = p;
        else if (s == 589824)    w4 = p;
        else if (s == 1179648)   w5 = p;
        else if (s == 2359296)   w6 = p;
        else if (s == 5120)      dw = p;
        else if (s == 10)        db = p;
        else if (bn_idx < 12)    bns[bn_idx++] = p;
    }

    conv1_kernel<<<1024, 128>>>(x, w1, b1, bns[0], bns[1]);
    pack_all_kernel<<<(142848 + 255) / 256, 256>>>(w2, w3, w4, w5, w6);

    // <W, CW, COUT, POOL, LAYER, PS>   grid = (COUT/32, 128, PS)
    bconv3_kernel<32, 4, 128, true,  2, 4><<<dim3(4, 128, 4), 128>>>(bns[2], bns[3]);
    bconv3_kernel<16, 4, 256, false, 3, 2><<<dim3(8, 128, 2), 128>>>(bns[4], bns[5]);
    bconv3_kernel<16, 8, 256, true,  4, 2><<<dim3(8, 128, 2), 128>>>(bns[6], bns[7]);
    bconv3_kernel<8, 8, 512, false, 5, 1><<<dim3(16, 128, 1), 128>>>(bns[8], bns[9]);
    bconv3_kernel<8, 16, 512, true,  6, 1><<<dim3(16, 128, 1), 128>>>(bns[10], bns[11]);

    dense_softmax_kernel<<<16, 128>>>(dw, db, (float*)d_out);
    (void)out_size;
}